// round 1
// baseline (speedup 1.0000x reference)
#include <cuda_runtime.h>
#include <math.h>

// ============================================================================
// CosFormer attention, fully fused pipeline:
//   1) gemm_ep<1,2,0>: Q/K/V projections with fused ReLU + cos/sin reweighting
//   2) chunk_stats:    per-chunk K^T V states + z sums (parallel over chunks)
//   3) chunk_scan:     exclusive prefix sum of states across chunks
//   4) attn_out:       per-chunk causal intra term + inter term, normalized
//   5) gemm_ep<3>:     output projection -> d_out
// All fp32; GEMMs use packed fma.rn.f32x2 (FFMA2) for 2x fp32 FMA throughput.
// ============================================================================

namespace cf {

constexpr int Bc = 2, Tc = 4096, Hc = 16, DHc = 64;
constexpr int DM = 1024, HD = 1024;            // d_model, H*dh
constexpr int Mrows = Bc * Tc;                 // 8192
constexpr int CH = 128, NCH = Tc / CH;         // chunk size, #chunks = 32
constexpr int BHc = Bc * Hc;                   // 32
constexpr float ANGC = 3.14159265358979323846f / (2.0f * (float)Tc);

// Scratch (device globals are the sanctioned alloc-free scratch mechanism)
__device__ __align__(16) float g_Qc[(size_t)Mrows * HD];
__device__ __align__(16) float g_Qs[(size_t)Mrows * HD];
__device__ __align__(16) float g_Kc[(size_t)Mrows * HD];
__device__ __align__(16) float g_Ks[(size_t)Mrows * HD];
__device__ __align__(16) float g_V [(size_t)Mrows * HD];
__device__ __align__(16) float g_attn[(size_t)Mrows * HD];
__device__ __align__(16) float g_Scos[(size_t)BHc * NCH * DHc * DHc];
__device__ __align__(16) float g_Ssin[(size_t)BHc * NCH * DHc * DHc];
__device__ __align__(16) float g_zcos[(size_t)BHc * NCH * DHc];
__device__ __align__(16) float g_zsin[(size_t)BHc * NCH * DHc];

// ---- packed f32x2 helpers -------------------------------------------------
__device__ __forceinline__ unsigned long long pack2(float lo, float hi) {
  unsigned long long r;
  asm("mov.b64 %0, {%1, %2};" : "=l"(r) : "f"(lo), "f"(hi));
  return r;
}
__device__ __forceinline__ void fma2(unsigned long long& d,
                                     unsigned long long a,
                                     unsigned long long b) {
  asm("fma.rn.f32x2 %0, %1, %2, %0;" : "+l"(d) : "l"(a), "l"(b));
}
__device__ __forceinline__ float2 unpack2(unsigned long long v) {
  float2 f;
  asm("mov.b64 {%0, %1}, %2;" : "=f"(f.x), "=f"(f.y) : "l"(v));
  return f;
}

// ============================================================================
// GEMM: C[M=8192, N=1024] = A @ W + bias, with per-mode epilogue.
// MODE 0: write V.  MODE 1: relu->cos/sin -> Qc,Qs.  MODE 2: -> Kc,Ks.
// MODE 3: A := g_attn, write final output (d_out).
// Tiling: 128x128 block, K-step 8, 256 threads, 8x8 per thread, double buffer.
// ============================================================================
template <int MODE>
__global__ __launch_bounds__(256, 2)
void gemm_ep(const float* __restrict__ A, const float* __restrict__ W,
             const float* __restrict__ bias, float* __restrict__ outO) {
  constexpr int K = 1024, N = 1024;
  __shared__ __align__(16) float As[2][8][128];   // As[buf][k][m] (transposed)
  __shared__ __align__(16) float Ws[2][8][128];   // Ws[buf][k][n]

  const float* Ain = (MODE == 3) ? g_attn : A;

  const int bm = blockIdx.y, bn = blockIdx.x;
  const int tid = threadIdx.x;
  const int tx = tid & 15, ty = tid >> 4;

  const float* Ab = Ain + (size_t)bm * 128 * K;
  const float* Wb = W + bn * 128;

  const int arow = tid >> 1, ac = (tid & 1) * 4;   // A tile: 128 rows x 8 cols
  const int wrow = tid >> 5, wc = (tid & 31) * 4;  // W tile: 8 rows x 128 cols

  float4 pa = *(const float4*)(Ab + (size_t)arow * K + ac);
  float4 pw = *(const float4*)(Wb + (size_t)wrow * N + wc);
  As[0][ac + 0][arow] = pa.x;
  As[0][ac + 1][arow] = pa.y;
  As[0][ac + 2][arow] = pa.z;
  As[0][ac + 3][arow] = pa.w;
  *(float4*)&Ws[0][wrow][wc] = pw;
  __syncthreads();

  unsigned long long acc[8][4];
#pragma unroll
  for (int i = 0; i < 8; ++i)
#pragma unroll
    for (int jj = 0; jj < 4; ++jj) acc[i][jj] = 0ull;  // bits of (0.f, 0.f)

  int cur = 0;
#pragma unroll 1
  for (int kt = 0; kt < K / 8; ++kt) {
    const bool more = (kt + 1 < K / 8);
    if (more) {
      const int k0 = (kt + 1) * 8;
      pa = *(const float4*)(Ab + (size_t)arow * K + k0 + ac);
      pw = *(const float4*)(Wb + (size_t)(k0 + wrow) * N + wc);
    }
#pragma unroll
    for (int k = 0; k < 8; ++k) {
      float4 a0 = *(const float4*)&As[cur][k][ty * 4];
      float4 a1 = *(const float4*)&As[cur][k][64 + ty * 4];
      float4 w0 = *(const float4*)&Ws[cur][k][tx * 4];
      float4 w1 = *(const float4*)&Ws[cur][k][64 + tx * 4];
      unsigned long long a2[8], w2[4];
      a2[0] = pack2(a0.x, a0.x); a2[1] = pack2(a0.y, a0.y);
      a2[2] = pack2(a0.z, a0.z); a2[3] = pack2(a0.w, a0.w);
      a2[4] = pack2(a1.x, a1.x); a2[5] = pack2(a1.y, a1.y);
      a2[6] = pack2(a1.z, a1.z); a2[7] = pack2(a1.w, a1.w);
      w2[0] = pack2(w0.x, w0.y); w2[1] = pack2(w0.z, w0.w);
      w2[2] = pack2(w1.x, w1.y); w2[3] = pack2(w1.z, w1.w);
#pragma unroll
      for (int i = 0; i < 8; ++i)
#pragma unroll
        for (int jj = 0; jj < 4; ++jj) fma2(acc[i][jj], a2[i], w2[jj]);
    }
    if (more) {
      const int nxt = cur ^ 1;
      As[nxt][ac + 0][arow] = pa.x;
      As[nxt][ac + 1][arow] = pa.y;
      As[nxt][ac + 2][arow] = pa.z;
      As[nxt][ac + 3][arow] = pa.w;
      *(float4*)&Ws[nxt][wrow][wc] = pw;
      __syncthreads();
      cur = nxt;
    }
  }

  // ---- epilogue ----
  const int nb0 = bn * 128 + tx * 4;
  const int nb1 = nb0 + 64;
  const float4 b0 = *(const float4*)&bias[nb0];
  const float4 b1 = *(const float4*)&bias[nb1];

#pragma unroll
  for (int i = 0; i < 8; ++i) {
    const int m = bm * 128 + ((i < 4) ? (ty * 4 + i) : (64 + ty * 4 + i - 4));
    float2 p0 = unpack2(acc[i][0]);
    float2 p1 = unpack2(acc[i][1]);
    float2 p2 = unpack2(acc[i][2]);
    float2 p3 = unpack2(acc[i][3]);
    float4 v0 = make_float4(p0.x + b0.x, p0.y + b0.y, p1.x + b0.z, p1.y + b0.w);
    float4 v1 = make_float4(p2.x + b1.x, p2.y + b1.y, p3.x + b1.z, p3.y + b1.w);

    if (MODE == 0) {
      *(float4*)&g_V[(size_t)m * HD + nb0] = v0;
      *(float4*)&g_V[(size_t)m * HD + nb1] = v1;
    } else if (MODE == 3) {
      *(float4*)&outO[(size_t)m * DM + nb0] = v0;
      *(float4*)&outO[(size_t)m * DM + nb1] = v1;
    } else {
      const int t = m & (Tc - 1);
      float sn, cs;
      sincosf(ANGC * (float)t, &sn, &cs);
      float4 r0 = make_float4(fmaxf(v0.x, 0.f), fmaxf(v0.y, 0.f),
                              fmaxf(v0.z, 0.f), fmaxf(v0.w, 0.f));
      float4 r1 = make_float4(fmaxf(v1.x, 0.f), fmaxf(v1.y, 0.f),
                              fmaxf(v1.z, 0.f), fmaxf(v1.w, 0.f));
      float4 c0 = make_float4(r0.x * cs, r0.y * cs, r0.z * cs, r0.w * cs);
      float4 c1 = make_float4(r1.x * cs, r1.y * cs, r1.z * cs, r1.w * cs);
      float4 s0 = make_float4(r0.x * sn, r0.y * sn, r0.z * sn, r0.w * sn);
      float4 s1 = make_float4(r1.x * sn, r1.y * sn, r1.z * sn, r1.w * sn);
      if (MODE == 1) {
        *(float4*)&g_Qc[(size_t)m * HD + nb0] = c0;
        *(float4*)&g_Qc[(size_t)m * HD + nb1] = c1;
        *(float4*)&g_Qs[(size_t)m * HD + nb0] = s0;
        *(float4*)&g_Qs[(size_t)m * HD + nb1] = s1;
      } else {
        *(float4*)&g_Kc[(size_t)m * HD + nb0] = c0;
        *(float4*)&g_Kc[(size_t)m * HD + nb1] = c1;
        *(float4*)&g_Ks[(size_t)m * HD + nb0] = s0;
        *(float4*)&g_Ks[(size_t)m * HD + nb1] = s1;
      }
    }
  }
}

// ============================================================================
// Pass A: per-chunk states  S_c = K_chunk^T @ V_chunk  (64x64), z_c = sum K.
// grid = B*H*NCH blocks, 256 threads, each thread a 4x4 micro-tile.
// ============================================================================
__global__ __launch_bounds__(256)
void chunk_stats() {
  const int blk = blockIdx.x;
  const int c = blk & (NCH - 1);
  const int bh = blk >> 5;                 // NCH == 32
  const int b = bh >> 4, h = bh & 15;      // H == 16
  const int tid = threadIdx.x, tx = tid & 15, ty = tid >> 4;

  __shared__ __align__(16) float sKc[32][64];
  __shared__ __align__(16) float sKs[32][64];
  __shared__ __align__(16) float sV[32][64];

  float aC[4][4] = {}, aS[4][4] = {};
  float zc[4] = {}, zs[4] = {};

  const size_t rowbase = ((size_t)b * Tc + (size_t)c * CH) * HD + h * DHc;

  for (int t0 = 0; t0 < CH; t0 += 32) {
    __syncthreads();
    for (int l = tid; l < 32 * 16; l += 256) {
      const int r = l >> 4, cc = (l & 15) << 2;
      const size_t g = rowbase + (size_t)(t0 + r) * HD + cc;
      *(float4*)&sKc[r][cc] = *(const float4*)&g_Kc[g];
      *(float4*)&sKs[r][cc] = *(const float4*)&g_Ks[g];
      *(float4*)&sV[r][cc] = *(const float4*)&g_V[g];
    }
    __syncthreads();
#pragma unroll 4
    for (int t = 0; t < 32; ++t) {
      float kc[4], ks[4], v[4];
#pragma unroll
      for (int i = 0; i < 4; ++i) {
        kc[i] = sKc[t][ty * 4 + i];
        ks[i] = sKs[t][ty * 4 + i];
      }
#pragma unroll
      for (int j = 0; j < 4; ++j) v[j] = sV[t][tx * 4 + j];
#pragma unroll
      for (int i = 0; i < 4; ++i)
#pragma unroll
        for (int j = 0; j < 4; ++j) {
          aC[i][j] += kc[i] * v[j];
          aS[i][j] += ks[i] * v[j];
        }
      if (tx == 0) {
#pragma unroll
        for (int i = 0; i < 4; ++i) { zc[i] += kc[i]; zs[i] += ks[i]; }
      }
    }
  }

  const size_t sb = ((size_t)bh * NCH + c) * (DHc * DHc);
#pragma unroll
  for (int i = 0; i < 4; ++i) {
    float4 vc = make_float4(aC[i][0], aC[i][1], aC[i][2], aC[i][3]);
    float4 vs = make_float4(aS[i][0], aS[i][1], aS[i][2], aS[i][3]);
    *(float4*)&g_Scos[sb + (size_t)(ty * 4 + i) * 64 + tx * 4] = vc;
    *(float4*)&g_Ssin[sb + (size_t)(ty * 4 + i) * 64 + tx * 4] = vs;
  }
  if (tx == 0) {
    const size_t zb = ((size_t)bh * NCH + c) * DHc;
#pragma unroll
    for (int i = 0; i < 4; ++i) {
      g_zcos[zb + ty * 4 + i] = zc[i];
      g_zsin[zb + ty * 4 + i] = zs[i];
    }
  }
}

// ============================================================================
// Pass B: in-place exclusive prefix sum of chunk states along the chunk axis.
// grid = B*H blocks.
// ============================================================================
__global__ __launch_bounds__(256)
void chunk_scan() {
  const int bh = blockIdx.x;
  const size_t base = (size_t)bh * NCH * (DHc * DHc);
  for (int e = threadIdx.x; e < DHc * DHc; e += 256) {
    float ac = 0.f, as2 = 0.f;
#pragma unroll 1
    for (int c = 0; c < NCH; ++c) {
      const size_t idx = base + (size_t)c * (DHc * DHc) + e;
      const float tc = g_Scos[idx], ts = g_Ssin[idx];
      g_Scos[idx] = ac;
      g_Ssin[idx] = as2;
      ac += tc;
      as2 += ts;
    }
  }
  const size_t zb = (size_t)bh * NCH * DHc;
  for (int e = threadIdx.x; e < DHc; e += 256) {
    float ac = 0.f, as2 = 0.f;
#pragma unroll 1
    for (int c = 0; c < NCH; ++c) {
      const size_t idx = zb + (size_t)c * DHc + e;
      const float tc = g_zcos[idx], ts = g_zsin[idx];
      g_zcos[idx] = ac;
      g_zsin[idx] = as2;
      ac += tc;
      as2 += ts;
    }
  }
}

// ============================================================================
// Pass C: per-chunk output.
//   A = tril(Qc Kc^T + Qs Ks^T) (128x128, s<=t inclusive)
//   num = A @ V + Qc @ Scos_prev + Qs @ Ssin_prev
//   den = rowsum(A) + Qc . zcos_prev + Qs . zsin_prev; out = num / max(den,1e-6)
// Dynamic smem ~196 KB, 1 block/SM, grid = 1024 blocks.
// ============================================================================
constexpr int SQ_LD = 65;
constexpr int SA_LD = 129;
constexpr int OFF_QC = 0;
constexpr int OFF_QS = CH * SQ_LD;         // 8320
constexpr int OFF_KC = 2 * CH * SQ_LD;     // 16640 (reused: V 128x64)
constexpr int OFF_KS = 3 * CH * SQ_LD;     // 24960 (reused: Scos+Ssin 2x64x64)
constexpr int OFF_A = 4 * CH * SQ_LD;      // 33280
constexpr int OFF_DEN = OFF_A + CH * SA_LD;
constexpr int OFF_ZC = OFF_DEN + CH;
constexpr int OFF_ZS = OFF_ZC + DHc;
constexpr int SMEM_FLOATS = OFF_ZS + DHc;  // 50048 floats = 200192 B

__global__ __launch_bounds__(256, 1)
void attn_out() {
  extern __shared__ __align__(16) float sm[];
  const int blk = blockIdx.x;
  const int c = blk & (NCH - 1);
  const int bh = blk >> 5;
  const int b = bh >> 4, h = bh & 15;
  const int tid = threadIdx.x, tx = tid & 15, ty = tid >> 4;

  float* sQc = sm + OFF_QC;
  float* sQs = sm + OFF_QS;
  float* sKc = sm + OFF_KC;
  float* sKs = sm + OFF_KS;
  float* sA = sm + OFF_A;
  float* sDen = sm + OFF_DEN;
  float* szc = sm + OFF_ZC;
  float* szs = sm + OFF_ZS;
  float* sV = sKc;                    // phase-2 reuse
  float* sScos = sKs;                 // phase-3 reuse
  float* sSsin = sKs + DHc * DHc;

  const size_t gbase = ((size_t)b * Tc + (size_t)c * CH) * HD + h * DHc;

  // load Qc,Qs,Kc,Ks tiles (128 x 64 each)
  for (int l = tid; l < CH * 16; l += 256) {
    const int r = l >> 4, cc = (l & 15) << 2;
    const size_t g = gbase + (size_t)r * HD + cc;
    float4 vq = *(const float4*)&g_Qc[g];
    float4 vs = *(const float4*)&g_Qs[g];
    float4 vk = *(const float4*)&g_Kc[g];
    float4 vx = *(const float4*)&g_Ks[g];
    float* p;
    p = &sQc[r * SQ_LD + cc]; p[0] = vq.x; p[1] = vq.y; p[2] = vq.z; p[3] = vq.w;
    p = &sQs[r * SQ_LD + cc]; p[0] = vs.x; p[1] = vs.y; p[2] = vs.z; p[3] = vs.w;
    p = &sKc[r * SQ_LD + cc]; p[0] = vk.x; p[1] = vk.y; p[2] = vk.z; p[3] = vk.w;
    p = &sKs[r * SQ_LD + cc]; p[0] = vx.x; p[1] = vx.y; p[2] = vx.z; p[3] = vx.w;
  }
  __syncthreads();

  // phase 1: A tile (skip strictly-upper blocks)
  const int t0 = ty * 8, s0 = tx * 8;
  float a[8][8] = {};
  if (tx <= ty) {
#pragma unroll 2
    for (int d = 0; d < DHc; ++d) {
      float qc[8], qs[8], kc[8], ks[8];
#pragma unroll
      for (int i = 0; i < 8; ++i) {
        qc[i] = sQc[(t0 + i) * SQ_LD + d];
        qs[i] = sQs[(t0 + i) * SQ_LD + d];
      }
#pragma unroll
      for (int j = 0; j < 8; ++j) {
        kc[j] = sKc[(s0 + j) * SQ_LD + d];
        ks[j] = sKs[(s0 + j) * SQ_LD + d];
      }
#pragma unroll
      for (int i = 0; i < 8; ++i)
#pragma unroll
        for (int j = 0; j < 8; ++j) {
          a[i][j] += qc[i] * kc[j];
          a[i][j] += qs[i] * ks[j];
        }
    }
  }
  // mask (s <= t), rowsum via shuffle over tx lanes, store A and den_intra
#pragma unroll
  for (int i = 0; i < 8; ++i) {
    const int t = t0 + i;
    float rs = 0.f;
#pragma unroll
    for (int j = 0; j < 8; ++j) {
      const float v = (s0 + j <= t) ? a[i][j] : 0.f;
      sA[t * SA_LD + s0 + j] = v;
      rs += v;
    }
    rs += __shfl_xor_sync(0xffffffffu, rs, 1);
    rs += __shfl_xor_sync(0xffffffffu, rs, 2);
    rs += __shfl_xor_sync(0xffffffffu, rs, 4);
    rs += __shfl_xor_sync(0xffffffffu, rs, 8);
    if (tx == 0) sDen[t] = rs;
  }
  __syncthreads();

  // load V (into Kc space), Scos/Ssin (into Ks space), z vectors
  for (int l = tid; l < CH * 16; l += 256) {
    const int r = l >> 4, cc = (l & 15) << 2;
    *(float4*)&sV[r * 64 + cc] =
        *(const float4*)&g_V[gbase + (size_t)r * HD + cc];
  }
  const size_t sb = ((size_t)bh * NCH + c) * (DHc * DHc);
  for (int l = tid; l < 64 * 16; l += 256) {
    const int r = l >> 4, cc = (l & 15) << 2;
    *(float4*)&sScos[r * 64 + cc] = *(const float4*)&g_Scos[sb + r * 64 + cc];
    *(float4*)&sSsin[r * 64 + cc] = *(const float4*)&g_Ssin[sb + r * 64 + cc];
  }
  if (tid < DHc) {
    const size_t zb = ((size_t)bh * NCH + c) * DHc;
    szc[tid] = g_zcos[zb + tid];
    szs[tid] = g_zsin[zb + tid];
  }
  __syncthreads();

  // phase 2 (intra: A @ V, only s < t0+8 needed) + phase 3 (inter: Q @ S_prev)
  float o[8][4] = {};
  float dden[8] = {};
  const int n0 = tx * 4;
  const int smax = t0 + 8;
#pragma unroll 2
  for (int s = 0; s < smax; ++s) {
    const float4 v4 = *(const float4*)&sV[s * 64 + n0];
#pragma unroll
    for (int i = 0; i < 8; ++i) {
      const float av = sA[(t0 + i) * SA_LD + s];
      o[i][0] += av * v4.x;
      o[i][1] += av * v4.y;
      o[i][2] += av * v4.z;
      o[i][3] += av * v4.w;
    }
  }
#pragma unroll 2
  for (int d = 0; d < DHc; ++d) {
    const float4 sc = *(const float4*)&sScos[d * 64 + n0];
    const float4 ss = *(const float4*)&sSsin[d * 64 + n0];
    const float zc = szc[d], zs = szs[d];
#pragma unroll
    for (int i = 0; i < 8; ++i) {
      const float qc = sQc[(t0 + i) * SQ_LD + d];
      const float qs = sQs[(t0 + i) * SQ_LD + d];
      o[i][0] += qc * sc.x + qs * ss.x;
      o[i][1] += qc * sc.y + qs * ss.y;
      o[i][2] += qc * sc.z + qs * ss.z;
      o[i][3] += qc * sc.w + qs * ss.w;
      dden[i] += qc * zc + qs * zs;
    }
  }
#pragma unroll
  for (int i = 0; i < 8; ++i) {
    const int t = t0 + i;
    float den = sDen[t] + dden[i];
    den = fmaxf(den, 1e-6f);
    const float inv = 1.0f / den;
    float4 res = make_float4(o[i][0] * inv, o[i][1] * inv,
                             o[i][2] * inv, o[i][3] * inv);
    *(float4*)&g_attn[gbase + (size_t)t * HD + n0] = res;
  }
}

}  // namespace cf

extern "C" void kernel_launch(void* const* d_in, const int* in_sizes, int n_in,
                              void* d_out, int out_size) {
  using namespace cf;
  const float* x = (const float*)d_in[0];
  const float* Wq = (const float*)d_in[1];
  const float* bq = (const float*)d_in[2];
  const float* Wk = (const float*)d_in[3];
  const float* bk = (const float*)d_in[4];
  const float* Wv = (const float*)d_in[5];
  const float* bv = (const float*)d_in[6];
  const float* Wo = (const float*)d_in[7];
  const float* bo = (const float*)d_in[8];
  float* out = (float*)d_out;

  dim3 gg(HD / 128, Mrows / 128);  // (8, 64)

  gemm_ep<1><<<gg, 256>>>(x, Wq, bq, nullptr);
  gemm_ep<2><<<gg, 256>>>(x, Wk, bk, nullptr);
  gemm_ep<0><<<gg, 256>>>(x, Wv, bv, nullptr);

  chunk_stats<<<BHc * NCH, 256>>>();
  chunk_scan<<<BHc, 256>>>();

  const size_t smem_bytes = (size_t)SMEM_FLOATS * sizeof(float);  // 200192
  cudaFuncSetAttribute(attn_out, cudaFuncAttributeMaxDynamicSharedMemorySize,
                       (int)smem_bytes);
  attn_out<<<BHc * NCH, 256, smem_bytes>>>();

  gemm_ep<3><<<gg, 256>>>(nullptr, Wo, bo, out);
}

// round 3
// speedup vs baseline: 1.3167x; 1.3167x over previous
#include <cuda_runtime.h>
#include <cuda_bf16.h>
#include <math.h>
#include <stdint.h>

// ============================================================================
// CosFormer attention on GB300 (compiled via compute_103 base target, so NO
// tcgen05 — use arch-portable mma.sync HMMA bf16 tensor cores instead).
//   GEMMs: mma.sync.m16n8k16 bf16 with bf16x3 fp32-emulation split:
//          x*w ~= xh*wh + xh*wl + xl*wh   (error ~2^-18, << 1e-3 gate)
//   Attention: chunked linear-attention (parallel, exact) in fp32.
// ============================================================================

namespace cf {

constexpr int Bc = 2, Tc = 4096, Hc = 16, DHc = 64;
constexpr int DM = 1024, HD = 1024;
constexpr int Mrows = Bc * Tc;            // 8192
constexpr int CH = 128, NCH = Tc / CH;    // 128, 32
constexpr int BHc = Bc * Hc;              // 32
constexpr float ANGC = 3.14159265358979323846f / (2.0f * (float)Tc);

constexpr int KDIM = 1024;
constexpr int KT = 64;                    // K elements per SMEM stage
constexpr int NKT = KDIM / KT;            // 16

// ---- fp32 scratch (attention path) ----
__device__ __align__(16) float g_Qc[(size_t)Mrows * HD];
__device__ __align__(16) float g_Qs[(size_t)Mrows * HD];
__device__ __align__(16) float g_Kc[(size_t)Mrows * HD];
__device__ __align__(16) float g_Ks[(size_t)Mrows * HD];
__device__ __align__(16) float g_V [(size_t)Mrows * HD];
__device__ __align__(16) float g_attn[(size_t)Mrows * HD];
__device__ __align__(16) float g_Scos[(size_t)BHc * NCH * DHc * DHc];
__device__ __align__(16) float g_Ssin[(size_t)BHc * NCH * DHc * DHc];
__device__ __align__(16) float g_zcos[(size_t)BHc * NCH * DHc];
__device__ __align__(16) float g_zsin[(size_t)BHc * NCH * DHc];

// ---- bf16 split operands ----
__device__ __align__(16) __nv_bfloat16 g_xh[(size_t)Mrows * DM];
__device__ __align__(16) __nv_bfloat16 g_xl[(size_t)Mrows * DM];
__device__ __align__(16) __nv_bfloat16 g_ah[(size_t)Mrows * HD];
__device__ __align__(16) __nv_bfloat16 g_al[(size_t)Mrows * HD];
__device__ __align__(16) __nv_bfloat16 g_Wqh[(size_t)HD * DM];
__device__ __align__(16) __nv_bfloat16 g_Wql[(size_t)HD * DM];
__device__ __align__(16) __nv_bfloat16 g_Wkh[(size_t)HD * DM];
__device__ __align__(16) __nv_bfloat16 g_Wkl[(size_t)HD * DM];
__device__ __align__(16) __nv_bfloat16 g_Wvh[(size_t)HD * DM];
__device__ __align__(16) __nv_bfloat16 g_Wvl[(size_t)HD * DM];
__device__ __align__(16) __nv_bfloat16 g_Woh[(size_t)DM * HD];
__device__ __align__(16) __nv_bfloat16 g_Wol[(size_t)DM * HD];

// ============================================================================
// helpers
// ============================================================================
__device__ __forceinline__ uint32_t smem_u32(const void* p) {
  uint32_t a;
  asm("{ .reg .u64 t; cvta.to.shared.u64 t, %1; cvt.u32.u64 %0, t; }"
      : "=r"(a) : "l"(p));
  return a;
}
__device__ __forceinline__ void ldsm4(uint32_t* r, uint32_t addr) {
  asm volatile(
      "ldmatrix.sync.aligned.m8n8.x4.shared.b16 {%0,%1,%2,%3}, [%4];"
      : "=r"(r[0]), "=r"(r[1]), "=r"(r[2]), "=r"(r[3]) : "r"(addr));
}
__device__ __forceinline__ void mma16816(float* d, const uint32_t* a,
                                         const uint32_t* b) {
  asm volatile(
      "mma.sync.aligned.m16n8k16.row.col.f32.bf16.bf16.f32 "
      "{%0,%1,%2,%3}, {%4,%5,%6,%7}, {%8,%9}, {%0,%1,%2,%3};"
      : "+f"(d[0]), "+f"(d[1]), "+f"(d[2]), "+f"(d[3])
      : "r"(a[0]), "r"(a[1]), "r"(a[2]), "r"(a[3]), "r"(b[0]), "r"(b[1]));
}
__device__ __forceinline__ void cpasync16(uint32_t dst, const void* src) {
  asm volatile("cp.async.cg.shared.global [%0], [%1], 16;"
               ::"r"(dst), "l"(src) : "memory");
}
__device__ __forceinline__ void cp_commit() {
  asm volatile("cp.async.commit_group;" ::: "memory");
}
template <int N>
__device__ __forceinline__ void cp_wait() {
  asm volatile("cp.async.wait_group %0;" ::"n"(N) : "memory");
}

// ============================================================================
// Split kernels: fp32 -> (bf16 hi, bf16 lo)
// ============================================================================
__global__ __launch_bounds__(256) void split_x(const float* __restrict__ in) {
  int i = blockIdx.x * 256 + threadIdx.x;  // n4 = Mrows*DM/4 exactly covered
  float4 v = *(const float4*)(in + (size_t)i * 4);
  __nv_bfloat16 h[4], l[4];
  float f[4] = {v.x, v.y, v.z, v.w};
#pragma unroll
  for (int j = 0; j < 4; ++j) {
    h[j] = __float2bfloat16(f[j]);
    l[j] = __float2bfloat16(f[j] - __bfloat162float(h[j]));
  }
  *(uint2*)(g_xh + (size_t)i * 4) = *(uint2*)h;
  *(uint2*)(g_xl + (size_t)i * 4) = *(uint2*)l;
}
__global__ __launch_bounds__(256) void split_attn() {
  int i = blockIdx.x * 256 + threadIdx.x;
  float4 v = *(const float4*)(g_attn + (size_t)i * 4);
  __nv_bfloat16 h[4], l[4];
  float f[4] = {v.x, v.y, v.z, v.w};
#pragma unroll
  for (int j = 0; j < 4; ++j) {
    h[j] = __float2bfloat16(f[j]);
    l[j] = __float2bfloat16(f[j] - __bfloat162float(h[j]));
  }
  *(uint2*)(g_ah + (size_t)i * 4) = *(uint2*)h;
  *(uint2*)(g_al + (size_t)i * 4) = *(uint2*)l;
}

// W[K=1024][N=1024] fp32 -> Wt[N][K] bf16 hi/lo.  WSEL: 0=q 1=k 2=v 3=o
template <int WSEL>
__global__ __launch_bounds__(256) void tsplit(const float* __restrict__ W) {
  __nv_bfloat16* Th = (WSEL == 0) ? g_Wqh : (WSEL == 1) ? g_Wkh
                        : (WSEL == 2) ? g_Wvh : g_Woh;
  __nv_bfloat16* Tl = (WSEL == 0) ? g_Wql : (WSEL == 1) ? g_Wkl
                        : (WSEL == 2) ? g_Wvl : g_Wol;
  __shared__ float tile[32][33];
  const int bx = blockIdx.x * 32, by = blockIdx.y * 32;
  const int tx = threadIdx.x, ty = threadIdx.y;  // (32, 8)
#pragma unroll
  for (int j = 0; j < 4; ++j)
    tile[ty + j * 8][tx] = W[(size_t)(by + ty + j * 8) * 1024 + bx + tx];
  __syncthreads();
#pragma unroll
  for (int j = 0; j < 4; ++j) {
    float v = tile[tx][ty + j * 8];
    __nv_bfloat16 h = __float2bfloat16(v);
    __nv_bfloat16 l = __float2bfloat16(v - __bfloat162float(h));
    const size_t o = (size_t)(bx + ty + j * 8) * 1024 + by + tx;
    Th[o] = h;
    Tl[o] = l;
  }
}

// ============================================================================
// HMMA GEMM: C[8192,1024] = A @ Wt^T  (Wt is [N,K] K-major), bf16x3 split.
// CTA 128x128, 8 warps (2x4) of 64x32, K staged 64 at a time, cp.async
// double buffer, XOR-128 swizzled SMEM + ldmatrix fragments.
// MODE 0: V.  MODE 1: relu+cos/sin -> Qc,Qs.  MODE 2: -> Kc,Ks.  MODE 3: out.
// ============================================================================
constexpr int PIECE_BYTES = 128 * KT * 2;         // 16384 per operand piece
constexpr int STAGE_BYTES = 4 * PIECE_BYTES;      // Ah,Al,Bh,Bl = 65536
constexpr int GEMM_SMEM = 2 * STAGE_BYTES;        // 131072

template <int MODE>
__global__ __launch_bounds__(256, 1) void gemm_mma(
    const float* __restrict__ bias, float* __restrict__ outO) {
  extern __shared__ __align__(16) char smem[];
  const uint32_t sb = smem_u32(smem);
  const int tid = threadIdx.x, wid = tid >> 5, lane = tid & 31;
  const int wm = wid >> 2, wn = wid & 3;  // warp tile: 64 rows x 32 cols
  const int bm = blockIdx.y, bn = blockIdx.x;

  // operand sources (selected at compile time, no host symbol lookup)
  const __nv_bfloat16* Ah = (MODE == 3) ? g_ah : g_xh;
  const __nv_bfloat16* Al = (MODE == 3) ? g_al : g_xl;
  const __nv_bfloat16* Bh = (MODE == 0) ? g_Wvh : (MODE == 1) ? g_Wqh
                              : (MODE == 2) ? g_Wkh : g_Woh;
  const __nv_bfloat16* Bl = (MODE == 0) ? g_Wvl : (MODE == 1) ? g_Wql
                              : (MODE == 2) ? g_Wkl : g_Wol;

  // ---- loader: piece p = tid>>6 (0:Ah 1:Al 2:Bh 3:Bl), q = tid&63 ----
  const int p = tid >> 6, q = tid & 63;
  const __nv_bfloat16* psrc;
  {
    const size_t arow = (size_t)bm * 128 * KDIM;
    const size_t brow = (size_t)bn * 128 * KDIM;
    psrc = (p == 0) ? Ah + arow : (p == 1) ? Al + arow
                                : (p == 2) ? Bh + brow : Bl + brow;
  }
  const __nv_bfloat16* gbase = psrc + (size_t)(q >> 3) * KDIM + (q & 7) * 8;
  const uint32_t loff0 = (uint32_t)((q >> 3) * 128 + (q & 7) * 16);

  auto issue = [&](int kt) {
    const int buf = kt & 1;
    const __nv_bfloat16* g = gbase + kt * KT;
    const uint32_t dstbase = sb + buf * STAGE_BYTES + p * PIECE_BYTES;
#pragma unroll
    for (int j = 0; j < 16; ++j) {
      const uint32_t off = loff0 + j * 1024;
      const uint32_t swz = off ^ ((off >> 3) & 0x70);
      cpasync16(dstbase + swz, g + (size_t)j * 8 * KDIM);
    }
    cp_commit();
  };

  float acc[4][4][4];
#pragma unroll
  for (int i = 0; i < 4; ++i)
#pragma unroll
    for (int j = 0; j < 4; ++j)
#pragma unroll
      for (int k = 0; k < 4; ++k) acc[i][j][k] = 0.f;

  issue(0);
#pragma unroll 1
  for (int kt = 0; kt < NKT; ++kt) {
    if (kt + 1 < NKT) {
      issue(kt + 1);
      cp_wait<1>();
    } else {
      cp_wait<0>();
    }
    __syncthreads();

    const uint32_t base = sb + (kt & 1) * STAGE_BYTES;
#pragma unroll
    for (int ks = 0; ks < 4; ++ks) {
      const int k0 = ks * 16;
      uint32_t ah[4][4], al[4][4], bh[2][4], bl[2][4];
#pragma unroll
      for (int mt = 0; mt < 4; ++mt) {
        const uint32_t row = wm * 64 + mt * 16 + (lane & 15);
        const uint32_t off = row * 128 + k0 * 2 + ((lane >> 4) << 4);
        const uint32_t swz = off ^ ((off >> 3) & 0x70);
        ldsm4(ah[mt], base + swz);
        ldsm4(al[mt], base + PIECE_BYTES + swz);
      }
#pragma unroll
      for (int nt2 = 0; nt2 < 2; ++nt2) {
        const uint32_t row =
            wn * 32 + nt2 * 16 + (lane & 7) + ((lane >> 4) << 3);
        const uint32_t off = row * 128 + k0 * 2 + (((lane >> 3) & 1) << 4);
        const uint32_t swz = off ^ ((off >> 3) & 0x70);
        ldsm4(bh[nt2], base + 2 * PIECE_BYTES + swz);
        ldsm4(bl[nt2], base + 3 * PIECE_BYTES + swz);
      }
#pragma unroll
      for (int mt = 0; mt < 4; ++mt)
#pragma unroll
        for (int nt = 0; nt < 4; ++nt) {
          const uint32_t* bhp = &bh[nt >> 1][(nt & 1) * 2];
          const uint32_t* blp = &bl[nt >> 1][(nt & 1) * 2];
          mma16816(acc[mt][nt], ah[mt], bhp);
          mma16816(acc[mt][nt], ah[mt], blp);
          mma16816(acc[mt][nt], al[mt], bhp);
        }
    }
    __syncthreads();
  }

  // ---- epilogue ----
  const int g = lane >> 2, t2 = (lane & 3) * 2;
#pragma unroll
  for (int mt = 0; mt < 4; ++mt) {
    const int r0 = bm * 128 + wm * 64 + mt * 16 + g;
    const int r1 = r0 + 8;
    float sn0 = 0.f, cs0 = 0.f, sn1 = 0.f, cs1 = 0.f;
    if (MODE == 1 || MODE == 2) {
      sincosf(ANGC * (float)(r0 & (Tc - 1)), &sn0, &cs0);
      sincosf(ANGC * (float)(r1 & (Tc - 1)), &sn1, &cs1);
    }
#pragma unroll
    for (int nt = 0; nt < 4; ++nt) {
      const int col = bn * 128 + wn * 32 + nt * 8 + t2;
      const float b0 = __ldg(&bias[col]), b1 = __ldg(&bias[col + 1]);
      const float v00 = acc[mt][nt][0] + b0, v01 = acc[mt][nt][1] + b1;
      const float v10 = acc[mt][nt][2] + b0, v11 = acc[mt][nt][3] + b1;
      if (MODE == 0) {
        *(float2*)&g_V[(size_t)r0 * HD + col] = make_float2(v00, v01);
        *(float2*)&g_V[(size_t)r1 * HD + col] = make_float2(v10, v11);
      } else if (MODE == 3) {
        *(float2*)&outO[(size_t)r0 * DM + col] = make_float2(v00, v01);
        *(float2*)&outO[(size_t)r1 * DM + col] = make_float2(v10, v11);
      } else {
        const float a00 = fmaxf(v00, 0.f), a01 = fmaxf(v01, 0.f);
        const float a10 = fmaxf(v10, 0.f), a11 = fmaxf(v11, 0.f);
        float* dc = (MODE == 1) ? g_Qc : g_Kc;
        float* ds = (MODE == 1) ? g_Qs : g_Ks;
        *(float2*)&dc[(size_t)r0 * HD + col] =
            make_float2(a00 * cs0, a01 * cs0);
        *(float2*)&dc[(size_t)r1 * HD + col] =
            make_float2(a10 * cs1, a11 * cs1);
        *(float2*)&ds[(size_t)r0 * HD + col] =
            make_float2(a00 * sn0, a01 * sn0);
        *(float2*)&ds[(size_t)r1 * HD + col] =
            make_float2(a10 * sn1, a11 * sn1);
      }
    }
  }
}

// ============================================================================
// Pass A: per-chunk states S_c = Kc^T V, Ks^T V (64x64), z = col-sums of K.
// ============================================================================
__global__ __launch_bounds__(256) void chunk_stats() {
  const int blk = blockIdx.x;
  const int c = blk & (NCH - 1);
  const int bh = blk >> 5;
  const int b = bh >> 4, h = bh & 15;
  const int tid = threadIdx.x, tx = tid & 15, ty = tid >> 4;

  __shared__ __align__(16) float sKc[32][64];
  __shared__ __align__(16) float sKs[32][64];
  __shared__ __align__(16) float sV[32][64];

  float aC[4][4] = {}, aS[4][4] = {};
  float zc[4] = {}, zs[4] = {};
  const size_t rowbase = ((size_t)b * Tc + (size_t)c * CH) * HD + h * DHc;

  for (int t0 = 0; t0 < CH; t0 += 32) {
    __syncthreads();
    for (int l = tid; l < 32 * 16; l += 256) {
      const int r = l >> 4, cc = (l & 15) << 2;
      const size_t g = rowbase + (size_t)(t0 + r) * HD + cc;
      *(float4*)&sKc[r][cc] = *(const float4*)&g_Kc[g];
      *(float4*)&sKs[r][cc] = *(const float4*)&g_Ks[g];
      *(float4*)&sV[r][cc] = *(const float4*)&g_V[g];
    }
    __syncthreads();
#pragma unroll 4
    for (int t = 0; t < 32; ++t) {
      float kc[4], ks[4], v[4];
#pragma unroll
      for (int i = 0; i < 4; ++i) {
        kc[i] = sKc[t][ty * 4 + i];
        ks[i] = sKs[t][ty * 4 + i];
      }
#pragma unroll
      for (int j = 0; j < 4; ++j) v[j] = sV[t][tx * 4 + j];
#pragma unroll
      for (int i = 0; i < 4; ++i)
#pragma unroll
        for (int j = 0; j < 4; ++j) {
          aC[i][j] += kc[i] * v[j];
          aS[i][j] += ks[i] * v[j];
        }
      if (tx == 0) {
#pragma unroll
        for (int i = 0; i < 4; ++i) { zc[i] += kc[i]; zs[i] += ks[i]; }
      }
    }
  }

  const size_t sbse = ((size_t)bh * NCH + c) * (DHc * DHc);
#pragma unroll
  for (int i = 0; i < 4; ++i) {
    *(float4*)&g_Scos[sbse + (size_t)(ty * 4 + i) * 64 + tx * 4] =
        make_float4(aC[i][0], aC[i][1], aC[i][2], aC[i][3]);
    *(float4*)&g_Ssin[sbse + (size_t)(ty * 4 + i) * 64 + tx * 4] =
        make_float4(aS[i][0], aS[i][1], aS[i][2], aS[i][3]);
  }
  if (tx == 0) {
    const size_t zb = ((size_t)bh * NCH + c) * DHc;
#pragma unroll
    for (int i = 0; i < 4; ++i) {
      g_zcos[zb + ty * 4 + i] = zc[i];
      g_zsin[zb + ty * 4 + i] = zs[i];
    }
  }
}

// ============================================================================
// Pass B: exclusive prefix over chunks. grid (16, 32) x 256 threads.
// ============================================================================
__global__ __launch_bounds__(256) void chunk_scan2() {
  const int bh = blockIdx.y;
  const int e = blockIdx.x * 256 + threadIdx.x;
  {
    const size_t base = (size_t)bh * NCH * (DHc * DHc) + e;
    float ac = 0.f, as2 = 0.f;
#pragma unroll 1
    for (int c = 0; c < NCH; ++c) {
      const size_t idx = base + (size_t)c * (DHc * DHc);
      const float tc = g_Scos[idx], ts = g_Ssin[idx];
      g_Scos[idx] = ac;
      g_Ssin[idx] = as2;
      ac += tc;
      as2 += ts;
    }
  }
  if (blockIdx.x == 0 && threadIdx.x < DHc) {
    const size_t zb = (size_t)bh * NCH * DHc + threadIdx.x;
    float ac = 0.f, as2 = 0.f;
#pragma unroll 1
    for (int c = 0; c < NCH; ++c) {
      const size_t idx = zb + (size_t)c * DHc;
      const float tc = g_zcos[idx], ts = g_zsin[idx];
      g_zcos[idx] = ac;
      g_zsin[idx] = as2;
      ac += tc;
      as2 += ts;
    }
  }
}

// ============================================================================
// Pass C: per-chunk output (intra causal + inter state), fp32.
// ============================================================================
constexpr int SQ_LD = 65;
constexpr int SA_LD = 129;
constexpr int OFF_QC = 0;
constexpr int OFF_QS = CH * SQ_LD;
constexpr int OFF_KC = 2 * CH * SQ_LD;
constexpr int OFF_KS = 3 * CH * SQ_LD;
constexpr int OFF_A = 4 * CH * SQ_LD;
constexpr int OFF_DEN = OFF_A + CH * SA_LD;
constexpr int OFF_ZC = OFF_DEN + CH;
constexpr int OFF_ZS = OFF_ZC + DHc;
constexpr int SMEM_FLOATS = OFF_ZS + DHc;

__global__ __launch_bounds__(256, 1) void attn_out() {
  extern __shared__ __align__(16) float sm[];
  const int blk = blockIdx.x;
  const int c = blk & (NCH - 1);
  const int bh = blk >> 5;
  const int b = bh >> 4, h = bh & 15;
  const int tid = threadIdx.x, tx = tid & 15, ty = tid >> 4;

  float* sQc = sm + OFF_QC;
  float* sQs = sm + OFF_QS;
  float* sKc = sm + OFF_KC;
  float* sKs = sm + OFF_KS;
  float* sA = sm + OFF_A;
  float* sDen = sm + OFF_DEN;
  float* szc = sm + OFF_ZC;
  float* szs = sm + OFF_ZS;
  float* sV = sKc;
  float* sScos = sKs;
  float* sSsin = sKs + DHc * DHc;

  const size_t gbase = ((size_t)b * Tc + (size_t)c * CH) * HD + h * DHc;

  for (int l = tid; l < CH * 16; l += 256) {
    const int r = l >> 4, cc = (l & 15) << 2;
    const size_t g = gbase + (size_t)r * HD + cc;
    float4 vq = *(const float4*)&g_Qc[g];
    float4 vs = *(const float4*)&g_Qs[g];
    float4 vk = *(const float4*)&g_Kc[g];
    float4 vx = *(const float4*)&g_Ks[g];
    float* pp;
    pp = &sQc[r * SQ_LD + cc]; pp[0]=vq.x; pp[1]=vq.y; pp[2]=vq.z; pp[3]=vq.w;
    pp = &sQs[r * SQ_LD + cc]; pp[0]=vs.x; pp[1]=vs.y; pp[2]=vs.z; pp[3]=vs.w;
    pp = &sKc[r * SQ_LD + cc]; pp[0]=vk.x; pp[1]=vk.y; pp[2]=vk.z; pp[3]=vk.w;
    pp = &sKs[r * SQ_LD + cc]; pp[0]=vx.x; pp[1]=vx.y; pp[2]=vx.z; pp[3]=vx.w;
  }
  __syncthreads();

  const int t0 = ty * 8, s0 = tx * 8;
  float a[8][8] = {};
  if (tx <= ty) {
#pragma unroll 2
    for (int d = 0; d < DHc; ++d) {
      float qc[8], qs[8], kc[8], ks[8];
#pragma unroll
      for (int i = 0; i < 8; ++i) {
        qc[i] = sQc[(t0 + i) * SQ_LD + d];
        qs[i] = sQs[(t0 + i) * SQ_LD + d];
      }
#pragma unroll
      for (int j = 0; j < 8; ++j) {
        kc[j] = sKc[(s0 + j) * SQ_LD + d];
        ks[j] = sKs[(s0 + j) * SQ_LD + d];
      }
#pragma unroll
      for (int i = 0; i < 8; ++i)
#pragma unroll
        for (int j = 0; j < 8; ++j) {
          a[i][j] += qc[i] * kc[j];
          a[i][j] += qs[i] * ks[j];
        }
    }
  }
#pragma unroll
  for (int i = 0; i < 8; ++i) {
    const int t = t0 + i;
    float rs = 0.f;
#pragma unroll
    for (int j = 0; j < 8; ++j) {
      const float v = (s0 + j <= t) ? a[i][j] : 0.f;
      sA[t * SA_LD + s0 + j] = v;
      rs += v;
    }
    rs += __shfl_xor_sync(0xffffffffu, rs, 1);
    rs += __shfl_xor_sync(0xffffffffu, rs, 2);
    rs += __shfl_xor_sync(0xffffffffu, rs, 4);
    rs += __shfl_xor_sync(0xffffffffu, rs, 8);
    if (tx == 0) sDen[t] = rs;
  }
  __syncthreads();

  for (int l = tid; l < CH * 16; l += 256) {
    const int r = l >> 4, cc = (l & 15) << 2;
    *(float4*)&sV[r * 64 + cc] =
        *(const float4*)&g_V[gbase + (size_t)r * HD + cc];
  }
  const size_t sbse = ((size_t)bh * NCH + c) * (DHc * DHc);
  for (int l = tid; l < 64 * 16; l += 256) {
    const int r = l >> 4, cc = (l & 15) << 2;
    *(float4*)&sScos[r * 64 + cc] = *(const float4*)&g_Scos[sbse + r * 64 + cc];
    *(float4*)&sSsin[r * 64 + cc] = *(const float4*)&g_Ssin[sbse + r * 64 + cc];
  }
  if (tid < DHc) {
    const size_t zb = ((size_t)bh * NCH + c) * DHc;
    szc[tid] = g_zcos[zb + tid];
    szs[tid] = g_zsin[zb + tid];
  }
  __syncthreads();

  float o[8][4] = {};
  float dden[8] = {};
  const int n0 = tx * 4;
  const int smax = t0 + 8;
#pragma unroll 2
  for (int s = 0; s < smax; ++s) {
    const float4 v4 = *(const float4*)&sV[s * 64 + n0];
#pragma unroll
    for (int i = 0; i < 8; ++i) {
      const float av = sA[(t0 + i) * SA_LD + s];
      o[i][0] += av * v4.x;
      o[i][1] += av * v4.y;
      o[i][2] += av * v4.z;
      o[i][3] += av * v4.w;
    }
  }
#pragma unroll 2
  for (int d = 0; d < DHc; ++d) {
    const float4 sc = *(const float4*)&sScos[d * 64 + n0];
    const float4 ss = *(const float4*)&sSsin[d * 64 + n0];
    const float zc = szc[d], zs = szs[d];
#pragma unroll
    for (int i = 0; i < 8; ++i) {
      const float qc = sQc[(t0 + i) * SQ_LD + d];
      const float qs = sQs[(t0 + i) * SQ_LD + d];
      o[i][0] += qc * sc.x + qs * ss.x;
      o[i][1] += qc * sc.y + qs * ss.y;
      o[i][2] += qc * sc.z + qs * ss.z;
      o[i][3] += qc * sc.w + qs * ss.w;
      dden[i] += qc * zc + qs * zs;
    }
  }
#pragma unroll
  for (int i = 0; i < 8; ++i) {
    const int t = t0 + i;
    float den = fmaxf(sDen[t] + dden[i], 1e-6f);
    const float inv = 1.0f / den;
    *(float4*)&g_attn[gbase + (size_t)t * HD + n0] =
        make_float4(o[i][0] * inv, o[i][1] * inv, o[i][2] * inv, o[i][3] * inv);
  }
}

}  // namespace cf

extern "C" void kernel_launch(void* const* d_in, const int* in_sizes, int n_in,
                              void* d_out, int out_size) {
  using namespace cf;
  const float* x = (const float*)d_in[0];
  const float* Wq = (const float*)d_in[1];
  const float* bq = (const float*)d_in[2];
  const float* Wk = (const float*)d_in[3];
  const float* bk = (const float*)d_in[4];
  const float* Wv = (const float*)d_in[5];
  const float* bv = (const float*)d_in[6];
  const float* Wo = (const float*)d_in[7];
  const float* bo = (const float*)d_in[8];
  float* out = (float*)d_out;

  cudaFuncSetAttribute(gemm_mma<0>, cudaFuncAttributeMaxDynamicSharedMemorySize, GEMM_SMEM);
  cudaFuncSetAttribute(gemm_mma<1>, cudaFuncAttributeMaxDynamicSharedMemorySize, GEMM_SMEM);
  cudaFuncSetAttribute(gemm_mma<2>, cudaFuncAttributeMaxDynamicSharedMemorySize, GEMM_SMEM);
  cudaFuncSetAttribute(gemm_mma<3>, cudaFuncAttributeMaxDynamicSharedMemorySize, GEMM_SMEM);
  cudaFuncSetAttribute(attn_out, cudaFuncAttributeMaxDynamicSharedMemorySize,
                       (int)(SMEM_FLOATS * sizeof(float)));

  // 1) splits
  split_x<<<Mrows * DM / 4 / 256, 256>>>(x);
  dim3 tg(32, 32), tb(32, 8);
  tsplit<0><<<tg, tb>>>(Wq);
  tsplit<1><<<tg, tb>>>(Wk);
  tsplit<2><<<tg, tb>>>(Wv);
  tsplit<3><<<tg, tb>>>(Wo);

  // 2) projection GEMMs (tensor cores via mma.sync)
  dim3 gg(HD / 128, Mrows / 128);  // (8, 64)
  gemm_mma<1><<<gg, 256, GEMM_SMEM>>>(bq, nullptr);
  gemm_mma<2><<<gg, 256, GEMM_SMEM>>>(bk, nullptr);
  gemm_mma<0><<<gg, 256, GEMM_SMEM>>>(bv, nullptr);

  // 3) attention
  chunk_stats<<<BHc * NCH, 256>>>();
  chunk_scan2<<<dim3(16, 32), 256>>>();
  attn_out<<<BHc * NCH, 256, SMEM_FLOATS * sizeof(float)>>>();

  // 4) output GEMM
  split_attn<<<Mrows * HD / 4 / 256, 256>>>();
  gemm_mma<3><<<gg, 256, GEMM_SMEM>>>(bo, out);
}

// round 4
// speedup vs baseline: 2.0000x; 1.5189x over previous
#include <cuda_runtime.h>
#include <cuda_bf16.h>
#include <math.h>
#include <stdint.h>

// ============================================================================
// CosFormer attention (sm_103 base target -> no tcgen05; mma.sync HMMA bf16).
//   GEMMs: mma.sync m16n8k16 bf16, bf16x3 fp32-emulation split
//          (x*w ~= xh*wh + xh*wl + xl*wh; err ~2^-18).
//   Round-4 changes: MMA term-pass reordering (break accumulator RAW chains),
//   fused QKV projection kernel (grid.z = 3).
// ============================================================================

namespace cf {

constexpr int Bc = 2, Tc = 4096, Hc = 16, DHc = 64;
constexpr int DM = 1024, HD = 1024;
constexpr int Mrows = Bc * Tc;            // 8192
constexpr int CH = 128, NCH = Tc / CH;    // 128, 32
constexpr int BHc = Bc * Hc;              // 32
constexpr float ANGC = 3.14159265358979323846f / (2.0f * (float)Tc);

constexpr int KDIM = 1024;
constexpr int KT = 64;                    // K elements per SMEM stage
constexpr int NKT = KDIM / KT;            // 16

// ---- fp32 scratch (attention path) ----
__device__ __align__(16) float g_Qc[(size_t)Mrows * HD];
__device__ __align__(16) float g_Qs[(size_t)Mrows * HD];
__device__ __align__(16) float g_Kc[(size_t)Mrows * HD];
__device__ __align__(16) float g_Ks[(size_t)Mrows * HD];
__device__ __align__(16) float g_V [(size_t)Mrows * HD];
__device__ __align__(16) float g_attn[(size_t)Mrows * HD];
__device__ __align__(16) float g_Scos[(size_t)BHc * NCH * DHc * DHc];
__device__ __align__(16) float g_Ssin[(size_t)BHc * NCH * DHc * DHc];
__device__ __align__(16) float g_zcos[(size_t)BHc * NCH * DHc];
__device__ __align__(16) float g_zsin[(size_t)BHc * NCH * DHc];

// ---- bf16 split operands ----
__device__ __align__(16) __nv_bfloat16 g_xh[(size_t)Mrows * DM];
__device__ __align__(16) __nv_bfloat16 g_xl[(size_t)Mrows * DM];
__device__ __align__(16) __nv_bfloat16 g_ah[(size_t)Mrows * HD];
__device__ __align__(16) __nv_bfloat16 g_al[(size_t)Mrows * HD];
__device__ __align__(16) __nv_bfloat16 g_Wqh[(size_t)HD * DM];
__device__ __align__(16) __nv_bfloat16 g_Wql[(size_t)HD * DM];
__device__ __align__(16) __nv_bfloat16 g_Wkh[(size_t)HD * DM];
__device__ __align__(16) __nv_bfloat16 g_Wkl[(size_t)HD * DM];
__device__ __align__(16) __nv_bfloat16 g_Wvh[(size_t)HD * DM];
__device__ __align__(16) __nv_bfloat16 g_Wvl[(size_t)HD * DM];
__device__ __align__(16) __nv_bfloat16 g_Woh[(size_t)DM * HD];
__device__ __align__(16) __nv_bfloat16 g_Wol[(size_t)DM * HD];

// ============================================================================
// helpers
// ============================================================================
__device__ __forceinline__ uint32_t smem_u32(const void* p) {
  uint32_t a;
  asm("{ .reg .u64 t; cvta.to.shared.u64 t, %1; cvt.u32.u64 %0, t; }"
      : "=r"(a) : "l"(p));
  return a;
}
__device__ __forceinline__ void ldsm4(uint32_t* r, uint32_t addr) {
  asm volatile(
      "ldmatrix.sync.aligned.m8n8.x4.shared.b16 {%0,%1,%2,%3}, [%4];"
      : "=r"(r[0]), "=r"(r[1]), "=r"(r[2]), "=r"(r[3]) : "r"(addr));
}
__device__ __forceinline__ void mma16816(float* d, const uint32_t* a,
                                         const uint32_t* b) {
  asm volatile(
      "mma.sync.aligned.m16n8k16.row.col.f32.bf16.bf16.f32 "
      "{%0,%1,%2,%3}, {%4,%5,%6,%7}, {%8,%9}, {%0,%1,%2,%3};"
      : "+f"(d[0]), "+f"(d[1]), "+f"(d[2]), "+f"(d[3])
      : "r"(a[0]), "r"(a[1]), "r"(a[2]), "r"(a[3]), "r"(b[0]), "r"(b[1]));
}
__device__ __forceinline__ void cpasync16(uint32_t dst, const void* src) {
  asm volatile("cp.async.cg.shared.global [%0], [%1], 16;"
               ::"r"(dst), "l"(src) : "memory");
}
__device__ __forceinline__ void cp_commit() {
  asm volatile("cp.async.commit_group;" ::: "memory");
}
template <int N>
__device__ __forceinline__ void cp_wait() {
  asm volatile("cp.async.wait_group %0;" ::"n"(N) : "memory");
}

// ============================================================================
// Split kernels: fp32 -> (bf16 hi, bf16 lo)
// ============================================================================
__global__ __launch_bounds__(256) void split_x(const float* __restrict__ in) {
  int i = blockIdx.x * 256 + threadIdx.x;
  float4 v = *(const float4*)(in + (size_t)i * 4);
  __nv_bfloat16 h[4], l[4];
  float f[4] = {v.x, v.y, v.z, v.w};
#pragma unroll
  for (int j = 0; j < 4; ++j) {
    h[j] = __float2bfloat16(f[j]);
    l[j] = __float2bfloat16(f[j] - __bfloat162float(h[j]));
  }
  *(uint2*)(g_xh + (size_t)i * 4) = *(uint2*)h;
  *(uint2*)(g_xl + (size_t)i * 4) = *(uint2*)l;
}
__global__ __launch_bounds__(256) void split_attn() {
  int i = blockIdx.x * 256 + threadIdx.x;
  float4 v = *(const float4*)(g_attn + (size_t)i * 4);
  __nv_bfloat16 h[4], l[4];
  float f[4] = {v.x, v.y, v.z, v.w};
#pragma unroll
  for (int j = 0; j < 4; ++j) {
    h[j] = __float2bfloat16(f[j]);
    l[j] = __float2bfloat16(f[j] - __bfloat162float(h[j]));
  }
  *(uint2*)(g_ah + (size_t)i * 4) = *(uint2*)h;
  *(uint2*)(g_al + (size_t)i * 4) = *(uint2*)l;
}

// W[K=1024][N=1024] fp32 -> Wt[N][K] bf16 hi/lo.  WSEL: 0=q 1=k 2=v 3=o
template <int WSEL>
__global__ __launch_bounds__(256) void tsplit(const float* __restrict__ W) {
  __nv_bfloat16* Th = (WSEL == 0) ? g_Wqh : (WSEL == 1) ? g_Wkh
                        : (WSEL == 2) ? g_Wvh : g_Woh;
  __nv_bfloat16* Tl = (WSEL == 0) ? g_Wql : (WSEL == 1) ? g_Wkl
                        : (WSEL == 2) ? g_Wvl : g_Wol;
  __shared__ float tile[32][33];
  const int bx = blockIdx.x * 32, by = blockIdx.y * 32;
  const int tx = threadIdx.x, ty = threadIdx.y;  // (32, 8)
#pragma unroll
  for (int j = 0; j < 4; ++j)
    tile[ty + j * 8][tx] = W[(size_t)(by + ty + j * 8) * 1024 + bx + tx];
  __syncthreads();
#pragma unroll
  for (int j = 0; j < 4; ++j) {
    float v = tile[tx][ty + j * 8];
    __nv_bfloat16 h = __float2bfloat16(v);
    __nv_bfloat16 l = __float2bfloat16(v - __bfloat162float(h));
    const size_t o = (size_t)(bx + ty + j * 8) * 1024 + by + tx;
    Th[o] = h;
    Tl[o] = l;
  }
}

// ============================================================================
// HMMA GEMM core (128x128 CTA tile, 8 warps of 64x32, K staged 64,
// cp.async double buffer, SW128 swizzle + ldmatrix).
// FUSED=1: QKV projections in one kernel (blockIdx.z selects weight set).
// FUSED=0: output projection.
// MMA inner loop runs three term-passes (hh, hl, lh) so consecutive MMAs on
// the same accumulator are 16 issues apart -> no RAW latency stalls.
// ============================================================================
constexpr int PIECE_BYTES = 128 * KT * 2;         // 16384
constexpr int STAGE_BYTES = 4 * PIECE_BYTES;      // 65536
constexpr int GEMM_SMEM = 2 * STAGE_BYTES;        // 131072

template <int FUSED>
__global__ __launch_bounds__(256, 1) void gemm_mma(
    const float* __restrict__ bias_q, const float* __restrict__ bias_k,
    const float* __restrict__ bias_v, float* __restrict__ outO) {
  extern __shared__ __align__(16) char smem[];
  const uint32_t sb = smem_u32(smem);
  const int tid = threadIdx.x, wid = tid >> 5, lane = tid & 31;
  const int wm = wid >> 2, wn = wid & 3;
  const int bm = blockIdx.y, bn = blockIdx.x;
  const int w = FUSED ? (int)blockIdx.z : 3;  // 0=Q 1=K 2=V 3=O

  const __nv_bfloat16* Ah = FUSED ? g_xh : g_ah;
  const __nv_bfloat16* Al = FUSED ? g_xl : g_al;
  const __nv_bfloat16* Bh = (w == 0) ? g_Wqh : (w == 1) ? g_Wkh
                              : (w == 2) ? g_Wvh : g_Woh;
  const __nv_bfloat16* Bl = (w == 0) ? g_Wql : (w == 1) ? g_Wkl
                              : (w == 2) ? g_Wvl : g_Wol;
  const float* bias = FUSED
                          ? ((w == 0) ? bias_q : (w == 1) ? bias_k : bias_v)
                          : bias_q;

  // ---- loader: piece p = tid>>6 (0:Ah 1:Al 2:Bh 3:Bl), q = tid&63 ----
  const int p = tid >> 6, q = tid & 63;
  const __nv_bfloat16* psrc;
  {
    const size_t arow = (size_t)bm * 128 * KDIM;
    const size_t brow = (size_t)bn * 128 * KDIM;
    psrc = (p == 0) ? Ah + arow : (p == 1) ? Al + arow
                                : (p == 2) ? Bh + brow : Bl + brow;
  }
  const __nv_bfloat16* gbase = psrc + (size_t)(q >> 3) * KDIM + (q & 7) * 8;
  const uint32_t loff0 = (uint32_t)((q >> 3) * 128 + (q & 7) * 16);

  auto issue = [&](int kt) {
    const int buf = kt & 1;
    const __nv_bfloat16* g = gbase + kt * KT;
    const uint32_t dstbase = sb + buf * STAGE_BYTES + p * PIECE_BYTES;
#pragma unroll
    for (int j = 0; j < 16; ++j) {
      const uint32_t off = loff0 + j * 1024;
      const uint32_t swz = off ^ ((off >> 3) & 0x70);
      cpasync16(dstbase + swz, g + (size_t)j * 8 * KDIM);
    }
    cp_commit();
  };

  float acc[4][4][4];
#pragma unroll
  for (int i = 0; i < 4; ++i)
#pragma unroll
    for (int j = 0; j < 4; ++j)
#pragma unroll
      for (int k = 0; k < 4; ++k) acc[i][j][k] = 0.f;

  issue(0);
#pragma unroll 1
  for (int kt = 0; kt < NKT; ++kt) {
    if (kt + 1 < NKT) {
      issue(kt + 1);
      cp_wait<1>();
    } else {
      cp_wait<0>();
    }
    __syncthreads();

    const uint32_t base = sb + (kt & 1) * STAGE_BYTES;
#pragma unroll
    for (int ks = 0; ks < 4; ++ks) {
      const int k0 = ks * 16;
      uint32_t ah[4][4], al[4][4], bh[2][4], bl[2][4];
#pragma unroll
      for (int mt = 0; mt < 4; ++mt) {
        const uint32_t row = wm * 64 + mt * 16 + (lane & 15);
        const uint32_t off = row * 128 + k0 * 2 + ((lane >> 4) << 4);
        const uint32_t swz = off ^ ((off >> 3) & 0x70);
        ldsm4(ah[mt], base + swz);
        ldsm4(al[mt], base + PIECE_BYTES + swz);
      }
#pragma unroll
      for (int nt2 = 0; nt2 < 2; ++nt2) {
        const uint32_t row =
            wn * 32 + nt2 * 16 + (lane & 7) + ((lane >> 4) << 3);
        const uint32_t off = row * 128 + k0 * 2 + (((lane >> 3) & 1) << 4);
        const uint32_t swz = off ^ ((off >> 3) & 0x70);
        ldsm4(bh[nt2], base + 2 * PIECE_BYTES + swz);
        ldsm4(bl[nt2], base + 3 * PIECE_BYTES + swz);
      }
      // --- term pass 1: ah * bh (16 independent MMAs) ---
#pragma unroll
      for (int mt = 0; mt < 4; ++mt)
#pragma unroll
        for (int nt = 0; nt < 4; ++nt)
          mma16816(acc[mt][nt], ah[mt], &bh[nt >> 1][(nt & 1) * 2]);
      // --- term pass 2: ah * bl ---
#pragma unroll
      for (int mt = 0; mt < 4; ++mt)
#pragma unroll
        for (int nt = 0; nt < 4; ++nt)
          mma16816(acc[mt][nt], ah[mt], &bl[nt >> 1][(nt & 1) * 2]);
      // --- term pass 3: al * bh ---
#pragma unroll
      for (int mt = 0; mt < 4; ++mt)
#pragma unroll
        for (int nt = 0; nt < 4; ++nt)
          mma16816(acc[mt][nt], al[mt], &bh[nt >> 1][(nt & 1) * 2]);
    }
    __syncthreads();
  }

  // ---- epilogue ----
  const int g = lane >> 2, t2 = (lane & 3) * 2;
#pragma unroll
  for (int mt = 0; mt < 4; ++mt) {
    const int r0 = bm * 128 + wm * 64 + mt * 16 + g;
    const int r1 = r0 + 8;
    float sn0 = 0.f, cs0 = 0.f, sn1 = 0.f, cs1 = 0.f;
    if (FUSED && w <= 1) {
      sincosf(ANGC * (float)(r0 & (Tc - 1)), &sn0, &cs0);
      sincosf(ANGC * (float)(r1 & (Tc - 1)), &sn1, &cs1);
    }
#pragma unroll
    for (int nt = 0; nt < 4; ++nt) {
      const int col = bn * 128 + wn * 32 + nt * 8 + t2;
      const float b0 = __ldg(&bias[col]), b1 = __ldg(&bias[col + 1]);
      const float v00 = acc[mt][nt][0] + b0, v01 = acc[mt][nt][1] + b1;
      const float v10 = acc[mt][nt][2] + b0, v11 = acc[mt][nt][3] + b1;
      if (!FUSED) {
        *(float2*)&outO[(size_t)r0 * DM + col] = make_float2(v00, v01);
        *(float2*)&outO[(size_t)r1 * DM + col] = make_float2(v10, v11);
      } else if (w == 2) {
        *(float2*)&g_V[(size_t)r0 * HD + col] = make_float2(v00, v01);
        *(float2*)&g_V[(size_t)r1 * HD + col] = make_float2(v10, v11);
      } else {
        const float a00 = fmaxf(v00, 0.f), a01 = fmaxf(v01, 0.f);
        const float a10 = fmaxf(v10, 0.f), a11 = fmaxf(v11, 0.f);
        float* dc = (w == 0) ? g_Qc : g_Kc;
        float* ds = (w == 0) ? g_Qs : g_Ks;
        *(float2*)&dc[(size_t)r0 * HD + col] =
            make_float2(a00 * cs0, a01 * cs0);
        *(float2*)&dc[(size_t)r1 * HD + col] =
            make_float2(a10 * cs1, a11 * cs1);
        *(float2*)&ds[(size_t)r0 * HD + col] =
            make_float2(a00 * sn0, a01 * sn0);
        *(float2*)&ds[(size_t)r1 * HD + col] =
            make_float2(a10 * sn1, a11 * sn1);
      }
    }
  }
}

// ============================================================================
// Pass A: per-chunk states S_c = Kc^T V, Ks^T V (64x64), z = col-sums of K.
// ============================================================================
__global__ __launch_bounds__(256) void chunk_stats() {
  const int blk = blockIdx.x;
  const int c = blk & (NCH - 1);
  const int bh = blk >> 5;
  const int b = bh >> 4, h = bh & 15;
  const int tid = threadIdx.x, tx = tid & 15, ty = tid >> 4;

  __shared__ __align__(16) float sKc[32][64];
  __shared__ __align__(16) float sKs[32][64];
  __shared__ __align__(16) float sV[32][64];

  float aC[4][4] = {}, aS[4][4] = {};
  float zc[4] = {}, zs[4] = {};
  const size_t rowbase = ((size_t)b * Tc + (size_t)c * CH) * HD + h * DHc;

  for (int t0 = 0; t0 < CH; t0 += 32) {
    __syncthreads();
    for (int l = tid; l < 32 * 16; l += 256) {
      const int r = l >> 4, cc = (l & 15) << 2;
      const size_t g = rowbase + (size_t)(t0 + r) * HD + cc;
      *(float4*)&sKc[r][cc] = *(const float4*)&g_Kc[g];
      *(float4*)&sKs[r][cc] = *(const float4*)&g_Ks[g];
      *(float4*)&sV[r][cc] = *(const float4*)&g_V[g];
    }
    __syncthreads();
#pragma unroll 4
    for (int t = 0; t < 32; ++t) {
      float kc[4], ks[4], v[4];
#pragma unroll
      for (int i = 0; i < 4; ++i) {
        kc[i] = sKc[t][ty * 4 + i];
        ks[i] = sKs[t][ty * 4 + i];
      }
#pragma unroll
      for (int j = 0; j < 4; ++j) v[j] = sV[t][tx * 4 + j];
#pragma unroll
      for (int i = 0; i < 4; ++i)
#pragma unroll
        for (int j = 0; j < 4; ++j) {
          aC[i][j] += kc[i] * v[j];
          aS[i][j] += ks[i] * v[j];
        }
      if (tx == 0) {
#pragma unroll
        for (int i = 0; i < 4; ++i) { zc[i] += kc[i]; zs[i] += ks[i]; }
      }
    }
  }

  const size_t sbse = ((size_t)bh * NCH + c) * (DHc * DHc);
#pragma unroll
  for (int i = 0; i < 4; ++i) {
    *(float4*)&g_Scos[sbse + (size_t)(ty * 4 + i) * 64 + tx * 4] =
        make_float4(aC[i][0], aC[i][1], aC[i][2], aC[i][3]);
    *(float4*)&g_Ssin[sbse + (size_t)(ty * 4 + i) * 64 + tx * 4] =
        make_float4(aS[i][0], aS[i][1], aS[i][2], aS[i][3]);
  }
  if (tx == 0) {
    const size_t zb = ((size_t)bh * NCH + c) * DHc;
#pragma unroll
    for (int i = 0; i < 4; ++i) {
      g_zcos[zb + ty * 4 + i] = zc[i];
      g_zsin[zb + ty * 4 + i] = zs[i];
    }
  }
}

// ============================================================================
// Pass B: exclusive prefix over chunks. grid (16, 32) x 256 threads.
// ============================================================================
__global__ __launch_bounds__(256) void chunk_scan2() {
  const int bh = blockIdx.y;
  const int e = blockIdx.x * 256 + threadIdx.x;
  {
    const size_t base = (size_t)bh * NCH * (DHc * DHc) + e;
    float ac = 0.f, as2 = 0.f;
#pragma unroll 1
    for (int c = 0; c < NCH; ++c) {
      const size_t idx = base + (size_t)c * (DHc * DHc);
      const float tc = g_Scos[idx], ts = g_Ssin[idx];
      g_Scos[idx] = ac;
      g_Ssin[idx] = as2;
      ac += tc;
      as2 += ts;
    }
  }
  if (blockIdx.x == 0 && threadIdx.x < DHc) {
    const size_t zb = (size_t)bh * NCH * DHc + threadIdx.x;
    float ac = 0.f, as2 = 0.f;
#pragma unroll 1
    for (int c = 0; c < NCH; ++c) {
      const size_t idx = zb + (size_t)c * DHc;
      const float tc = g_zcos[idx], ts = g_zsin[idx];
      g_zcos[idx] = ac;
      g_zsin[idx] = as2;
      ac += tc;
      as2 += ts;
    }
  }
}

// ============================================================================
// Pass C: per-chunk output (intra causal + inter state), fp32.
// ============================================================================
constexpr int SQ_LD = 65;
constexpr int SA_LD = 129;
constexpr int OFF_QC = 0;
constexpr int OFF_QS = CH * SQ_LD;
constexpr int OFF_KC = 2 * CH * SQ_LD;
constexpr int OFF_KS = 3 * CH * SQ_LD;
constexpr int OFF_A = 4 * CH * SQ_LD;
constexpr int OFF_DEN = OFF_A + CH * SA_LD;
constexpr int OFF_ZC = OFF_DEN + CH;
constexpr int OFF_ZS = OFF_ZC + DHc;
constexpr int SMEM_FLOATS = OFF_ZS + DHc;

__global__ __launch_bounds__(256, 1) void attn_out() {
  extern __shared__ __align__(16) float sm[];
  const int blk = blockIdx.x;
  const int c = blk & (NCH - 1);
  const int bh = blk >> 5;
  const int b = bh >> 4, h = bh & 15;
  const int tid = threadIdx.x, tx = tid & 15, ty = tid >> 4;

  float* sQc = sm + OFF_QC;
  float* sQs = sm + OFF_QS;
  float* sKc = sm + OFF_KC;
  float* sKs = sm + OFF_KS;
  float* sA = sm + OFF_A;
  float* sDen = sm + OFF_DEN;
  float* szc = sm + OFF_ZC;
  float* szs = sm + OFF_ZS;
  float* sV = sKc;
  float* sScos = sKs;
  float* sSsin = sKs + DHc * DHc;

  const size_t gbase = ((size_t)b * Tc + (size_t)c * CH) * HD + h * DHc;

  for (int l = tid; l < CH * 16; l += 256) {
    const int r = l >> 4, cc = (l & 15) << 2;
    const size_t g = gbase + (size_t)r * HD + cc;
    float4 vq = *(const float4*)&g_Qc[g];
    float4 vs = *(const float4*)&g_Qs[g];
    float4 vk = *(const float4*)&g_Kc[g];
    float4 vx = *(const float4*)&g_Ks[g];
    float* pp;
    pp = &sQc[r * SQ_LD + cc]; pp[0]=vq.x; pp[1]=vq.y; pp[2]=vq.z; pp[3]=vq.w;
    pp = &sQs[r * SQ_LD + cc]; pp[0]=vs.x; pp[1]=vs.y; pp[2]=vs.z; pp[3]=vs.w;
    pp = &sKc[r * SQ_LD + cc]; pp[0]=vk.x; pp[1]=vk.y; pp[2]=vk.z; pp[3]=vk.w;
    pp = &sKs[r * SQ_LD + cc]; pp[0]=vx.x; pp[1]=vx.y; pp[2]=vx.z; pp[3]=vx.w;
  }
  __syncthreads();

  const int t0 = ty * 8, s0 = tx * 8;
  float a[8][8] = {};
  if (tx <= ty) {
#pragma unroll 2
    for (int d = 0; d < DHc; ++d) {
      float qc[8], qs[8], kc[8], ks[8];
#pragma unroll
      for (int i = 0; i < 8; ++i) {
        qc[i] = sQc[(t0 + i) * SQ_LD + d];
        qs[i] = sQs[(t0 + i) * SQ_LD + d];
      }
#pragma unroll
      for (int j = 0; j < 8; ++j) {
        kc[j] = sKc[(s0 + j) * SQ_LD + d];
        ks[j] = sKs[(s0 + j) * SQ_LD + d];
      }
#pragma unroll
      for (int i = 0; i < 8; ++i)
#pragma unroll
        for (int j = 0; j < 8; ++j) {
          a[i][j] += qc[i] * kc[j];
          a[i][j] += qs[i] * ks[j];
        }
    }
  }
#pragma unroll
  for (int i = 0; i < 8; ++i) {
    const int t = t0 + i;
    float rs = 0.f;
#pragma unroll
    for (int j = 0; j < 8; ++j) {
      const float v = (s0 + j <= t) ? a[i][j] : 0.f;
      sA[t * SA_LD + s0 + j] = v;
      rs += v;
    }
    rs += __shfl_xor_sync(0xffffffffu, rs, 1);
    rs += __shfl_xor_sync(0xffffffffu, rs, 2);
    rs += __shfl_xor_sync(0xffffffffu, rs, 4);
    rs += __shfl_xor_sync(0xffffffffu, rs, 8);
    if (tx == 0) sDen[t] = rs;
  }
  __syncthreads();

  for (int l = tid; l < CH * 16; l += 256) {
    const int r = l >> 4, cc = (l & 15) << 2;
    *(float4*)&sV[r * 64 + cc] =
        *(const float4*)&g_V[gbase + (size_t)r * HD + cc];
  }
  const size_t sbse = ((size_t)bh * NCH + c) * (DHc * DHc);
  for (int l = tid; l < 64 * 16; l += 256) {
    const int r = l >> 4, cc = (l & 15) << 2;
    *(float4*)&sScos[r * 64 + cc] = *(const float4*)&g_Scos[sbse + r * 64 + cc];
    *(float4*)&sSsin[r * 64 + cc] = *(const float4*)&g_Ssin[sbse + r * 64 + cc];
  }
  if (tid < DHc) {
    const size_t zb = ((size_t)bh * NCH + c) * DHc;
    szc[tid] = g_zcos[zb + tid];
    szs[tid] = g_zsin[zb + tid];
  }
  __syncthreads();

  float o[8][4] = {};
  float dden[8] = {};
  const int n0 = tx * 4;
  const int smax = t0 + 8;
#pragma unroll 2
  for (int s = 0; s < smax; ++s) {
    const float4 v4 = *(const float4*)&sV[s * 64 + n0];
#pragma unroll
    for (int i = 0; i < 8; ++i) {
      const float av = sA[(t0 + i) * SA_LD + s];
      o[i][0] += av * v4.x;
      o[i][1] += av * v4.y;
      o[i][2] += av * v4.z;
      o[i][3] += av * v4.w;
    }
  }
#pragma unroll 2
  for (int d = 0; d < DHc; ++d) {
    const float4 sc = *(const float4*)&sScos[d * 64 + n0];
    const float4 ss = *(const float4*)&sSsin[d * 64 + n0];
    const float zc = szc[d], zs = szs[d];
#pragma unroll
    for (int i = 0; i < 8; ++i) {
      const float qc = sQc[(t0 + i) * SQ_LD + d];
      const float qs = sQs[(t0 + i) * SQ_LD + d];
      o[i][0] += qc * sc.x + qs * ss.x;
      o[i][1] += qc * sc.y + qs * ss.y;
      o[i][2] += qc * sc.z + qs * ss.z;
      o[i][3] += qc * sc.w + qs * ss.w;
      dden[i] += qc * zc + qs * zs;
    }
  }
#pragma unroll
  for (int i = 0; i < 8; ++i) {
    const int t = t0 + i;
    float den = fmaxf(sDen[t] + dden[i], 1e-6f);
    const float inv = 1.0f / den;
    *(float4*)&g_attn[gbase + (size_t)t * HD + n0] =
        make_float4(o[i][0] * inv, o[i][1] * inv, o[i][2] * inv, o[i][3] * inv);
  }
}

}  // namespace cf

extern "C" void kernel_launch(void* const* d_in, const int* in_sizes, int n_in,
                              void* d_out, int out_size) {
  using namespace cf;
  const float* x = (const float*)d_in[0];
  const float* Wq = (const float*)d_in[1];
  const float* bq = (const float*)d_in[2];
  const float* Wk = (const float*)d_in[3];
  const float* bk = (const float*)d_in[4];
  const float* Wv = (const float*)d_in[5];
  const float* bv = (const float*)d_in[6];
  const float* Wo = (const float*)d_in[7];
  const float* bo = (const float*)d_in[8];
  float* out = (float*)d_out;

  cudaFuncSetAttribute(gemm_mma<1>, cudaFuncAttributeMaxDynamicSharedMemorySize, GEMM_SMEM);
  cudaFuncSetAttribute(gemm_mma<0>, cudaFuncAttributeMaxDynamicSharedMemorySize, GEMM_SMEM);
  cudaFuncSetAttribute(attn_out, cudaFuncAttributeMaxDynamicSharedMemorySize,
                       (int)(SMEM_FLOATS * sizeof(float)));

  // 1) splits
  split_x<<<Mrows * DM / 4 / 256, 256>>>(x);
  dim3 tg(32, 32), tb(32, 8);
  tsplit<0><<<tg, tb>>>(Wq);
  tsplit<1><<<tg, tb>>>(Wk);
  tsplit<2><<<tg, tb>>>(Wv);
  tsplit<3><<<tg, tb>>>(Wo);

  // 2) fused QKV projection GEMMs (tensor cores)
  dim3 gq(HD / 128, Mrows / 128, 3);  // (8, 64, 3)
  gemm_mma<1><<<gq, 256, GEMM_SMEM>>>(bq, bk, bv, nullptr);

  // 3) attention
  chunk_stats<<<BHc * NCH, 256>>>();
  chunk_scan2<<<dim3(16, 32), 256>>>();
  attn_out<<<BHc * NCH, 256, SMEM_FLOATS * sizeof(float)>>>();

  // 4) output GEMM
  split_attn<<<Mrows * HD / 4 / 256, 256>>>();
  dim3 go(HD / 128, Mrows / 128, 1);
  gemm_mma<0><<<go, 256, GEMM_SMEM>>>(bo, nullptr, nullptr, out);
}